// round 2
// baseline (speedup 1.0000x reference)
#include <cuda_runtime.h>

#define N_NODES 100000
#define N_EDGES 1600000
#define D 64

// Scratch (allocation-free: __device__ globals)
__device__ float g_agg[(size_t)N_NODES * D];
__device__ float g_h1[(size_t)N_NODES * D];
__device__ float g_deg[N_NODES];

// ---------------------------------------------------------------------------
// Zero scratch: agg always; deg optionally (first layer only)
// ---------------------------------------------------------------------------
__global__ void zero_kernel(int zero_deg) {
    int idx = blockIdx.x * blockDim.x + threadIdx.x;
    const int n4 = N_NODES * D / 4;
    if (idx < n4) {
        reinterpret_cast<float4*>(g_agg)[idx] = make_float4(0.f, 0.f, 0.f, 0.f);
    }
    if (zero_deg && idx < N_NODES) {
        g_deg[idx] = 0.f;
    }
}

// ---------------------------------------------------------------------------
// Edge scatter: agg[dst] += feat[src]  (vectorized red.global.add.v4.f32)
// Each warp handles 2 edges: lanes [0..15] -> edge A, [16..31] -> edge B.
// Each lane moves one float4 (16B) of the 256B feature row.
// Layer 1 also accumulates in-degree.
// NOTE: edge_index is int32 (JAX default config downgrades int64).
// ---------------------------------------------------------------------------
template <bool WITH_DEG, bool FEAT_IS_H1>
__global__ void scatter_kernel(const float* __restrict__ x,
                               const int* __restrict__ src,
                               const int* __restrict__ dst) {
    const float* feat = FEAT_IS_H1 ? g_h1 : x;
    int gwarp = (blockIdx.x * blockDim.x + threadIdx.x) >> 5;
    int lane = threadIdx.x & 31;
    int e = gwarp * 2 + (lane >> 4);
    if (e >= N_EDGES) return;
    int c = lane & 15;

    const int s = src[e];
    const int d = dst[e];

    const float4 v = *reinterpret_cast<const float4*>(feat + (size_t)s * D + c * 4);
    float* p = g_agg + (size_t)d * D + c * 4;
    asm volatile("red.global.add.v4.f32 [%0], {%1, %2, %3, %4};"
                 :: "l"(p), "f"(v.x), "f"(v.y), "f"(v.z), "f"(v.w)
                 : "memory");
    if (WITH_DEG && c == 0) {
        atomicAdd(g_deg + d, 1.0f);
    }
}

// ---------------------------------------------------------------------------
// Per-node dense kernel:
//   y = relu( (agg * inv_deg) @ Wl + bl + feat @ Wr )
// FINAL=false: feat = x (param), write y to g_h1
// FINAL=true : feat = g_h1,     out[n] = y @ Wfc + bfc  (h2 never stored)
//
// Block = 256 threads = 8 warps; each warp owns 4 nodes (32 nodes/block).
// Thread t of a warp computes output columns j=t and j=t+32 for its 4 nodes.
// Weights live in shared; per-node input rows are broadcast via __shfl_sync.
// ---------------------------------------------------------------------------
template <bool FINAL>
__global__ void __launch_bounds__(256) node_kernel(
    const float* __restrict__ xin,
    const float* __restrict__ Wl,
    const float* __restrict__ bl,
    const float* __restrict__ Wr,
    const float* __restrict__ Wfc,
    const float* __restrict__ bfc,
    float* __restrict__ outp) {
    __shared__ float sWl[D * D];
    __shared__ float sWr[D * D];
    __shared__ float sb[D];
    __shared__ float sfc[D];

    const int tid = threadIdx.x;
#pragma unroll
    for (int i = tid; i < D * D; i += 256) {
        sWl[i] = Wl[i];
        sWr[i] = Wr[i];
    }
    if (tid < D) {
        sb[tid] = bl[tid];
        sfc[tid] = FINAL ? Wfc[tid] : 0.f;
    }
    __syncthreads();

    const float* feat = FINAL ? g_h1 : xin;

    const int warp = tid >> 5;
    const int lane = tid & 31;
    const int nbase = (blockIdx.x * 8 + warp) * 4;  // 4 nodes per warp

    float x0[4], x1[4], a0[4], a1[4];
    float acc0[4], acc1[4];
    const float b0 = sb[lane];
    const float b1 = sb[lane + 32];

#pragma unroll
    for (int i = 0; i < 4; i++) {
        const int n = nbase + i;
        const float dg = g_deg[n];
        const float invd = dg > 0.f ? 1.0f / dg : 0.f;
        x0[i] = feat[(size_t)n * D + lane];
        x1[i] = feat[(size_t)n * D + 32 + lane];
        a0[i] = g_agg[(size_t)n * D + lane] * invd;
        a1[i] = g_agg[(size_t)n * D + 32 + lane] * invd;
        acc0[i] = b0;
        acc1[i] = b1;
    }

#pragma unroll 8
    for (int k = 0; k < 32; k++) {
        const float wl00 = sWl[k * D + lane];
        const float wl01 = sWl[k * D + 32 + lane];
        const float wl10 = sWl[(k + 32) * D + lane];
        const float wl11 = sWl[(k + 32) * D + 32 + lane];
        const float wr00 = sWr[k * D + lane];
        const float wr01 = sWr[k * D + 32 + lane];
        const float wr10 = sWr[(k + 32) * D + lane];
        const float wr11 = sWr[(k + 32) * D + 32 + lane];
#pragma unroll
        for (int i = 0; i < 4; i++) {
            const float ak = __shfl_sync(0xFFFFFFFFu, a0[i], k);
            const float ak2 = __shfl_sync(0xFFFFFFFFu, a1[i], k);
            const float xk = __shfl_sync(0xFFFFFFFFu, x0[i], k);
            const float xk2 = __shfl_sync(0xFFFFFFFFu, x1[i], k);
            acc0[i] += ak * wl00 + ak2 * wl10 + xk * wr00 + xk2 * wr10;
            acc1[i] += ak * wl01 + ak2 * wl11 + xk * wr01 + xk2 * wr11;
        }
    }

    if (!FINAL) {
#pragma unroll
        for (int i = 0; i < 4; i++) {
            const int n = nbase + i;
            g_h1[(size_t)n * D + lane] = fmaxf(acc0[i], 0.f);
            g_h1[(size_t)n * D + 32 + lane] = fmaxf(acc1[i], 0.f);
        }
    } else {
        const float w0 = sfc[lane];
        const float w1 = sfc[lane + 32];
        const float bias = bfc[0];
#pragma unroll
        for (int i = 0; i < 4; i++) {
            float p = fmaxf(acc0[i], 0.f) * w0 + fmaxf(acc1[i], 0.f) * w1;
#pragma unroll
            for (int off = 16; off > 0; off >>= 1) {
                p += __shfl_xor_sync(0xFFFFFFFFu, p, off);
            }
            if (lane == 0) outp[nbase + i] = p + bias;
        }
    }
}

// ---------------------------------------------------------------------------
// Launch
// ---------------------------------------------------------------------------
extern "C" void kernel_launch(void* const* d_in, const int* in_sizes, int n_in,
                              void* d_out, int out_size) {
    const float* x = (const float*)d_in[0];
    const int* ei = (const int*)d_in[1];
    const float* Wl1 = (const float*)d_in[2];
    const float* bl1 = (const float*)d_in[3];
    const float* Wr1 = (const float*)d_in[4];
    const float* Wl2 = (const float*)d_in[5];
    const float* bl2 = (const float*)d_in[6];
    const float* Wr2 = (const float*)d_in[7];
    const float* Wfc = (const float*)d_in[8];
    const float* bfc = (const float*)d_in[9];
    float* out = (float*)d_out;

    const int* src = ei;
    const int* dst = ei + N_EDGES;

    const int zero_blocks = (N_NODES * D / 4 + 255) / 256;     // covers agg (and deg)
    const int scatter_blocks = (N_EDGES + 15) / 16;            // 16 edges per 256-thr block
    const int node_blocks = N_NODES / 32;                      // 3125, exact

    // Layer 1
    zero_kernel<<<zero_blocks, 256>>>(1);
    scatter_kernel<true, false><<<scatter_blocks, 256>>>(x, src, dst);
    node_kernel<false><<<node_blocks, 256>>>(x, Wl1, bl1, Wr1, nullptr, nullptr, nullptr);

    // Layer 2 + head
    zero_kernel<<<zero_blocks, 256>>>(0);
    scatter_kernel<false, true><<<scatter_blocks, 256>>>(x, src, dst);
    node_kernel<true><<<node_blocks, 256>>>(x, Wl2, bl2, Wr2, Wfc, bfc, out);
}

// round 3
// speedup vs baseline: 1.3491x; 1.3491x over previous
#include <cuda_runtime.h>

#define N_NODES 100000
#define N_EDGES 1600000
#define D 64
#define NBLK_SCAN ((N_NODES + 1023) / 1024)   // 98

// Scratch (allocation-free: __device__ globals)
__device__ float g_agg[(size_t)N_NODES * D];   // pre-scaled mean aggregate
__device__ float g_h1[(size_t)N_NODES * D];
__device__ int   g_count[N_NODES];
__device__ int   g_off[N_NODES + 1];
__device__ int   g_cursor[N_NODES];
__device__ int   g_nbr[N_EDGES];
__device__ float g_inv[N_NODES];
__device__ int   g_blocksums[NBLK_SCAN];

// ---------------------------------------------------------------------------
// CSR construction (by destination)
// ---------------------------------------------------------------------------
__global__ void zero_count_kernel() {
    int i = blockIdx.x * blockDim.x + threadIdx.x;
    if (i < N_NODES) g_count[i] = 0;
}

__global__ void hist_kernel(const int* __restrict__ dst) {
    int e = blockIdx.x * blockDim.x + threadIdx.x;
    if (e < N_EDGES) atomicAdd(&g_count[dst[e]], 1);
}

__global__ void __launch_bounds__(1024) scan_block_kernel() {
    __shared__ int sh[1024];
    int gi = blockIdx.x * 1024 + threadIdx.x;
    int v = (gi < N_NODES) ? g_count[gi] : 0;
    sh[threadIdx.x] = v;
    __syncthreads();
#pragma unroll
    for (int off = 1; off < 1024; off <<= 1) {
        int t = (threadIdx.x >= off) ? sh[threadIdx.x - off] : 0;
        __syncthreads();
        sh[threadIdx.x] += t;
        __syncthreads();
    }
    int incl = sh[threadIdx.x];
    if (gi < N_NODES) g_off[gi] = incl - v;   // exclusive within block
    if (threadIdx.x == 1023) g_blocksums[blockIdx.x] = incl;
}

__global__ void scan_top_kernel() {
    if (threadIdx.x == 0 && blockIdx.x == 0) {
        int running = 0;
        for (int i = 0; i < NBLK_SCAN; i++) {
            int t = g_blocksums[i];
            g_blocksums[i] = running;
            running += t;
        }
    }
}

__global__ void scan_finish_kernel() {
    int gi = blockIdx.x * blockDim.x + threadIdx.x;
    if (gi < N_NODES) {
        int o = g_off[gi] + g_blocksums[gi >> 10];
        g_off[gi] = o;
        g_cursor[gi] = o;
        int c = g_count[gi];
        g_inv[gi] = c > 0 ? 1.0f / (float)c : 0.f;
    }
    if (gi == 0) g_off[N_NODES] = N_EDGES;
}

__global__ void fill_kernel(const int* __restrict__ src,
                            const int* __restrict__ dst) {
    int e = blockIdx.x * blockDim.x + threadIdx.x;
    if (e < N_EDGES) {
        int p = atomicAdd(&g_cursor[dst[e]], 1);
        g_nbr[p] = src[e];
    }
}

// ---------------------------------------------------------------------------
// Gather-aggregate: agg[n] = inv_deg[n] * sum_{s in nbr(n)} feat[s]
// One warp per node. Two neighbors per iteration (half-warps), float4 lanes.
// ---------------------------------------------------------------------------
template <bool FEAT_IS_H1>
__global__ void __launch_bounds__(256) gather_kernel(const float* __restrict__ x) {
    const float* feat = FEAT_IS_H1 ? g_h1 : x;
    const int gwarp = (blockIdx.x * blockDim.x + threadIdx.x) >> 5;
    if (gwarp >= N_NODES) return;
    const int n = gwarp;
    const int lane = threadIdx.x & 31;
    const int half = lane >> 4;
    const int c = lane & 15;

    const int start = g_off[n];
    const int end = g_off[n + 1];

    float4 acc = make_float4(0.f, 0.f, 0.f, 0.f);
    for (int j = start + half; j < end; j += 2) {
        const int s = g_nbr[j];
        const float4 v = *reinterpret_cast<const float4*>(feat + (size_t)s * D + c * 4);
        acc.x += v.x; acc.y += v.y; acc.z += v.z; acc.w += v.w;
    }
    acc.x += __shfl_down_sync(0xFFFFFFFFu, acc.x, 16);
    acc.y += __shfl_down_sync(0xFFFFFFFFu, acc.y, 16);
    acc.z += __shfl_down_sync(0xFFFFFFFFu, acc.z, 16);
    acc.w += __shfl_down_sync(0xFFFFFFFFu, acc.w, 16);

    if (half == 0) {
        const float inv = g_inv[n];
        acc.x *= inv; acc.y *= inv; acc.z *= inv; acc.w *= inv;
        *reinterpret_cast<float4*>(g_agg + (size_t)n * D + c * 4) = acc;
    }
}

// ---------------------------------------------------------------------------
// Per-node dense kernel:
//   y = relu( agg @ Wl + bl + feat @ Wr )          (agg already mean-scaled)
// FINAL=false: feat = x, write y to g_h1
// FINAL=true : feat = g_h1, out[n] = y @ Wfc + bfc
// Block = 256 = 8 warps; each warp owns 4 nodes; weights in shared;
// node rows broadcast via shfl.
// ---------------------------------------------------------------------------
template <bool FINAL>
__global__ void __launch_bounds__(256) node_kernel(
    const float* __restrict__ xin,
    const float* __restrict__ Wl,
    const float* __restrict__ bl,
    const float* __restrict__ Wr,
    const float* __restrict__ Wfc,
    const float* __restrict__ bfc,
    float* __restrict__ outp) {
    __shared__ float sWl[D * D];
    __shared__ float sWr[D * D];
    __shared__ float sb[D];
    __shared__ float sfc[D];

    const int tid = threadIdx.x;
#pragma unroll
    for (int i = tid; i < D * D; i += 256) {
        sWl[i] = Wl[i];
        sWr[i] = Wr[i];
    }
    if (tid < D) {
        sb[tid] = bl[tid];
        sfc[tid] = FINAL ? Wfc[tid] : 0.f;
    }
    __syncthreads();

    const float* feat = FINAL ? g_h1 : xin;

    const int warp = tid >> 5;
    const int lane = tid & 31;
    const int nbase = (blockIdx.x * 8 + warp) * 4;

    float x0[4], x1[4], a0[4], a1[4];
    float acc0[4], acc1[4];
    const float b0 = sb[lane];
    const float b1 = sb[lane + 32];

#pragma unroll
    for (int i = 0; i < 4; i++) {
        const int n = nbase + i;
        x0[i] = feat[(size_t)n * D + lane];
        x1[i] = feat[(size_t)n * D + 32 + lane];
        a0[i] = g_agg[(size_t)n * D + lane];
        a1[i] = g_agg[(size_t)n * D + 32 + lane];
        acc0[i] = b0;
        acc1[i] = b1;
    }

#pragma unroll 8
    for (int k = 0; k < 32; k++) {
        const float wl00 = sWl[k * D + lane];
        const float wl01 = sWl[k * D + 32 + lane];
        const float wl10 = sWl[(k + 32) * D + lane];
        const float wl11 = sWl[(k + 32) * D + 32 + lane];
        const float wr00 = sWr[k * D + lane];
        const float wr01 = sWr[k * D + 32 + lane];
        const float wr10 = sWr[(k + 32) * D + lane];
        const float wr11 = sWr[(k + 32) * D + 32 + lane];
#pragma unroll
        for (int i = 0; i < 4; i++) {
            const float ak = __shfl_sync(0xFFFFFFFFu, a0[i], k);
            const float ak2 = __shfl_sync(0xFFFFFFFFu, a1[i], k);
            const float xk = __shfl_sync(0xFFFFFFFFu, x0[i], k);
            const float xk2 = __shfl_sync(0xFFFFFFFFu, x1[i], k);
            acc0[i] += ak * wl00 + ak2 * wl10 + xk * wr00 + xk2 * wr10;
            acc1[i] += ak * wl01 + ak2 * wl11 + xk * wr01 + xk2 * wr11;
        }
    }

    if (!FINAL) {
#pragma unroll
        for (int i = 0; i < 4; i++) {
            const int n = nbase + i;
            g_h1[(size_t)n * D + lane] = fmaxf(acc0[i], 0.f);
            g_h1[(size_t)n * D + 32 + lane] = fmaxf(acc1[i], 0.f);
        }
    } else {
        const float w0 = sfc[lane];
        const float w1 = sfc[lane + 32];
        const float bias = bfc[0];
#pragma unroll
        for (int i = 0; i < 4; i++) {
            float p = fmaxf(acc0[i], 0.f) * w0 + fmaxf(acc1[i], 0.f) * w1;
#pragma unroll
            for (int off = 16; off > 0; off >>= 1) {
                p += __shfl_xor_sync(0xFFFFFFFFu, p, off);
            }
            if (lane == 0) outp[nbase + i] = p + bias;
        }
    }
}

// ---------------------------------------------------------------------------
// Launch
// ---------------------------------------------------------------------------
extern "C" void kernel_launch(void* const* d_in, const int* in_sizes, int n_in,
                              void* d_out, int out_size) {
    const float* x = (const float*)d_in[0];
    const int* ei = (const int*)d_in[1];
    const float* Wl1 = (const float*)d_in[2];
    const float* bl1 = (const float*)d_in[3];
    const float* Wr1 = (const float*)d_in[4];
    const float* Wl2 = (const float*)d_in[5];
    const float* bl2 = (const float*)d_in[6];
    const float* Wr2 = (const float*)d_in[7];
    const float* Wfc = (const float*)d_in[8];
    const float* bfc = (const float*)d_in[9];
    float* out = (float*)d_out;

    const int* src = ei;
    const int* dst = ei + N_EDGES;

    const int nblk = (N_NODES + 255) / 256;
    const int eblk = (N_EDGES + 255) / 256;
    const int gather_blocks = (N_NODES + 7) / 8;   // 8 warps/block, warp per node
    const int node_blocks = N_NODES / 32;          // 3125, exact

    // CSR build (once per call; reused by both layers)
    zero_count_kernel<<<nblk, 256>>>();
    hist_kernel<<<eblk, 256>>>(dst);
    scan_block_kernel<<<NBLK_SCAN, 1024>>>();
    scan_top_kernel<<<1, 32>>>();
    scan_finish_kernel<<<nblk, 256>>>();
    fill_kernel<<<eblk, 256>>>(src, dst);

    // Layer 1
    gather_kernel<false><<<gather_blocks, 256>>>(x);
    node_kernel<false><<<node_blocks, 256>>>(x, Wl1, bl1, Wr1, nullptr, nullptr, nullptr);

    // Layer 2 + head
    gather_kernel<true><<<gather_blocks, 256>>>(x);
    node_kernel<true><<<node_blocks, 256>>>(x, Wl2, bl2, Wr2, Wfc, bfc, out);
}

// round 4
// speedup vs baseline: 1.4087x; 1.0442x over previous
#include <cuda_runtime.h>

#define N_NODES 100000
#define N_EDGES 1600000
#define D 64
#define NBLK_SCAN ((N_NODES + 1023) / 1024)   // 98

// Scratch (allocation-free: __device__ globals)
__device__ float g_h1[(size_t)N_NODES * D];
__device__ int   g_count[N_NODES];
__device__ int   g_off[N_NODES + 1];
__device__ int   g_cursor[N_NODES];
__device__ int   g_nbr[N_EDGES];
__device__ float g_inv[N_NODES];
__device__ int   g_blocksums[NBLK_SCAN];

// ---------------------------------------------------------------------------
// CSR construction (by destination)
// ---------------------------------------------------------------------------
__global__ void zero_count_kernel() {
    int i = blockIdx.x * blockDim.x + threadIdx.x;
    if (i < N_NODES) g_count[i] = 0;
}

__global__ void hist_kernel(const int* __restrict__ dst) {
    int e = blockIdx.x * blockDim.x + threadIdx.x;
    if (e < N_EDGES) atomicAdd(&g_count[dst[e]], 1);
}

__global__ void __launch_bounds__(1024) scan_block_kernel() {
    __shared__ int sh[1024];
    int gi = blockIdx.x * 1024 + threadIdx.x;
    int v = (gi < N_NODES) ? g_count[gi] : 0;
    sh[threadIdx.x] = v;
    __syncthreads();
#pragma unroll
    for (int off = 1; off < 1024; off <<= 1) {
        int t = (threadIdx.x >= off) ? sh[threadIdx.x - off] : 0;
        __syncthreads();
        sh[threadIdx.x] += t;
        __syncthreads();
    }
    int incl = sh[threadIdx.x];
    if (gi < N_NODES) g_off[gi] = incl - v;   // exclusive within block
    if (threadIdx.x == 1023) g_blocksums[blockIdx.x] = incl;
}

// Parallel scan over the 98 block sums (one 128-thread block, Hillis-Steele)
__global__ void __launch_bounds__(128) scan_top_kernel() {
    __shared__ int sh[128];
    int i = threadIdx.x;
    int v = (i < NBLK_SCAN) ? g_blocksums[i] : 0;
    sh[i] = v;
    __syncthreads();
#pragma unroll
    for (int off = 1; off < 128; off <<= 1) {
        int t = (i >= off) ? sh[i - off] : 0;
        __syncthreads();
        sh[i] += t;
        __syncthreads();
    }
    if (i < NBLK_SCAN) g_blocksums[i] = sh[i] - v;  // exclusive
}

__global__ void scan_finish_kernel() {
    int gi = blockIdx.x * blockDim.x + threadIdx.x;
    if (gi < N_NODES) {
        int o = g_off[gi] + g_blocksums[gi >> 10];
        g_off[gi] = o;
        g_cursor[gi] = o;
        int c = g_count[gi];
        g_inv[gi] = c > 0 ? 1.0f / (float)c : 0.f;
    }
    if (gi == 0) g_off[N_NODES] = N_EDGES;
}

__global__ void fill_kernel(const int* __restrict__ src,
                            const int* __restrict__ dst) {
    int e = blockIdx.x * blockDim.x + threadIdx.x;
    if (e < N_EDGES) {
        int p = atomicAdd(&g_cursor[dst[e]], 1);
        g_nbr[p] = src[e];
    }
}

// ---------------------------------------------------------------------------
// Fused gather + dense kernel:
//   agg[n] = inv_deg[n] * sum_{s in nbr(n)} feat[s]      (staged in shared)
//   y      = relu( agg @ Wl + bl + feat @ Wr )
// FINAL=false: feat = x, write y to g_h1
// FINAL=true : feat = g_h1, out[n] = y @ Wfc + bfc
//
// Block = 256 threads = 8 warps, 32 nodes/block.
// Phase 1: each warp gathers its 4 nodes into sAgg (16 lanes per row,
//          2 edges in flight per half-warp via 2-way unroll).
// Phase 2: dual matmul with weights in shared, rows broadcast via shfl.
// ---------------------------------------------------------------------------
template <bool FINAL>
__global__ void __launch_bounds__(256) fused_node_kernel(
    const float* __restrict__ xin,
    const float* __restrict__ Wl,
    const float* __restrict__ bl,
    const float* __restrict__ Wr,
    const float* __restrict__ Wfc,
    const float* __restrict__ bfc,
    float* __restrict__ outp) {
    __shared__ float sWl[D * D];
    __shared__ float sWr[D * D];
    __shared__ float sb[D];
    __shared__ float sfc[D];
    __shared__ float sAgg[32 * D];   // 8 KB

    const int tid = threadIdx.x;
#pragma unroll
    for (int i = tid; i < D * D; i += 256) {
        sWl[i] = Wl[i];
        sWr[i] = Wr[i];
    }
    if (tid < D) {
        sb[tid] = bl[tid];
        sfc[tid] = FINAL ? Wfc[tid] : 0.f;
    }

    const float* feat = FINAL ? g_h1 : xin;
    const float4* feat4 = reinterpret_cast<const float4*>(feat);

    const int warp = tid >> 5;
    const int lane = tid & 31;
    const int nbase = blockIdx.x * 32 + warp * 4;   // 4 nodes per warp

    // ---- Phase 1: gather into shared ----
    const int half = lane >> 4;
    const int c = lane & 15;
#pragma unroll
    for (int i = 0; i < 4; i++) {
        const int n = nbase + i;
        const int start = g_off[n];
        const int end = g_off[n + 1];

        float4 acc0 = make_float4(0.f, 0.f, 0.f, 0.f);
        float4 acc1 = make_float4(0.f, 0.f, 0.f, 0.f);
        int j = start + half;
        for (; j + 2 < end; j += 4) {
            const int s0 = g_nbr[j];
            const int s1 = g_nbr[j + 2];
            const float4 v0 = feat4[(size_t)s0 * 16 + c];
            const float4 v1 = feat4[(size_t)s1 * 16 + c];
            acc0.x += v0.x; acc0.y += v0.y; acc0.z += v0.z; acc0.w += v0.w;
            acc1.x += v1.x; acc1.y += v1.y; acc1.z += v1.z; acc1.w += v1.w;
        }
        if (j < end) {
            const int s = g_nbr[j];
            const float4 v = feat4[(size_t)s * 16 + c];
            acc0.x += v.x; acc0.y += v.y; acc0.z += v.z; acc0.w += v.w;
        }
        acc0.x += acc1.x; acc0.y += acc1.y; acc0.z += acc1.z; acc0.w += acc1.w;
        acc0.x += __shfl_down_sync(0xFFFFFFFFu, acc0.x, 16);
        acc0.y += __shfl_down_sync(0xFFFFFFFFu, acc0.y, 16);
        acc0.z += __shfl_down_sync(0xFFFFFFFFu, acc0.z, 16);
        acc0.w += __shfl_down_sync(0xFFFFFFFFu, acc0.w, 16);
        if (half == 0) {
            const float inv = g_inv[n];
            acc0.x *= inv; acc0.y *= inv; acc0.z *= inv; acc0.w *= inv;
            *reinterpret_cast<float4*>(sAgg + (warp * 4 + i) * D + c * 4) = acc0;
        }
    }
    __syncthreads();

    // ---- Phase 2: dense ----
    float x0[4], x1[4], a0[4], a1[4];
    float acc0[4], acc1[4];
    const float b0 = sb[lane];
    const float b1 = sb[lane + 32];

#pragma unroll
    for (int i = 0; i < 4; i++) {
        const int n = nbase + i;
        x0[i] = feat[(size_t)n * D + lane];
        x1[i] = feat[(size_t)n * D + 32 + lane];
        a0[i] = sAgg[(warp * 4 + i) * D + lane];
        a1[i] = sAgg[(warp * 4 + i) * D + 32 + lane];
        acc0[i] = b0;
        acc1[i] = b1;
    }

#pragma unroll 8
    for (int k = 0; k < 32; k++) {
        const float wl00 = sWl[k * D + lane];
        const float wl01 = sWl[k * D + 32 + lane];
        const float wl10 = sWl[(k + 32) * D + lane];
        const float wl11 = sWl[(k + 32) * D + 32 + lane];
        const float wr00 = sWr[k * D + lane];
        const float wr01 = sWr[k * D + 32 + lane];
        const float wr10 = sWr[(k + 32) * D + lane];
        const float wr11 = sWr[(k + 32) * D + 32 + lane];
#pragma unroll
        for (int i = 0; i < 4; i++) {
            const float ak = __shfl_sync(0xFFFFFFFFu, a0[i], k);
            const float ak2 = __shfl_sync(0xFFFFFFFFu, a1[i], k);
            const float xk = __shfl_sync(0xFFFFFFFFu, x0[i], k);
            const float xk2 = __shfl_sync(0xFFFFFFFFu, x1[i], k);
            acc0[i] += ak * wl00 + ak2 * wl10 + xk * wr00 + xk2 * wr10;
            acc1[i] += ak * wl01 + ak2 * wl11 + xk * wr01 + xk2 * wr11;
        }
    }

    if (!FINAL) {
#pragma unroll
        for (int i = 0; i < 4; i++) {
            const int n = nbase + i;
            g_h1[(size_t)n * D + lane] = fmaxf(acc0[i], 0.f);
            g_h1[(size_t)n * D + 32 + lane] = fmaxf(acc1[i], 0.f);
        }
    } else {
        const float w0 = sfc[lane];
        const float w1 = sfc[lane + 32];
        const float bias = bfc[0];
#pragma unroll
        for (int i = 0; i < 4; i++) {
            float p = fmaxf(acc0[i], 0.f) * w0 + fmaxf(acc1[i], 0.f) * w1;
#pragma unroll
            for (int off = 16; off > 0; off >>= 1) {
                p += __shfl_xor_sync(0xFFFFFFFFu, p, off);
            }
            if (lane == 0) outp[nbase + i] = p + bias;
        }
    }
}

// ---------------------------------------------------------------------------
// Launch
// ---------------------------------------------------------------------------
extern "C" void kernel_launch(void* const* d_in, const int* in_sizes, int n_in,
                              void* d_out, int out_size) {
    const float* x = (const float*)d_in[0];
    const int* ei = (const int*)d_in[1];
    const float* Wl1 = (const float*)d_in[2];
    const float* bl1 = (const float*)d_in[3];
    const float* Wr1 = (const float*)d_in[4];
    const float* Wl2 = (const float*)d_in[5];
    const float* bl2 = (const float*)d_in[6];
    const float* Wr2 = (const float*)d_in[7];
    const float* Wfc = (const float*)d_in[8];
    const float* bfc = (const float*)d_in[9];
    float* out = (float*)d_out;

    const int* src = ei;
    const int* dst = ei + N_EDGES;

    const int nblk = (N_NODES + 255) / 256;
    const int eblk = (N_EDGES + 255) / 256;
    const int node_blocks = N_NODES / 32;          // 3125, exact

    // CSR build (once per call; reused by both layers)
    zero_count_kernel<<<nblk, 256>>>();
    hist_kernel<<<eblk, 256>>>(dst);
    scan_block_kernel<<<NBLK_SCAN, 1024>>>();
    scan_top_kernel<<<1, 128>>>();
    scan_finish_kernel<<<nblk, 256>>>();
    fill_kernel<<<eblk, 256>>>(src, dst);

    // Layer 1 (fused gather + dense)
    fused_node_kernel<false><<<node_blocks, 256>>>(x, Wl1, bl1, Wr1, nullptr, nullptr, nullptr);

    // Layer 2 + head (fused gather + dense)
    fused_node_kernel<true><<<node_blocks, 256>>>(x, Wl2, bl2, Wr2, Wfc, bfc, out);
}

// round 6
// speedup vs baseline: 1.5535x; 1.1028x over previous
#include <cuda_runtime.h>
#include <cuda_bf16.h>
#include <cstdint>

#define N_NODES 100000
#define N_EDGES 1600000
#define D 64
#define TILE_M 128
#define NBLK_SCAN ((N_NODES + 1023) / 1024)   // 98
#define NODE_BLOCKS ((N_NODES + TILE_M - 1) / TILE_M)  // 782

#define A_STRIDE 136   // halves per A row (128 + 8 pad)
#define B_STRIDE 136   // halves per B row (128 + 8 pad)

// SMEM layout (bytes, dynamic)
#define SM_BIAS 0
#define SM_FC   256
#define SM_OUT  512
#define SM_AHI  1024
#define SM_ALO  (SM_AHI + 128 * A_STRIDE * 2)   // +34816
#define SM_BHI  (SM_ALO + 128 * A_STRIDE * 2)
#define SM_BLO  (SM_BHI + 64 * B_STRIDE * 2)    // +17408
#define SMEM_TOTAL (SM_BLO + 64 * B_STRIDE * 2) // 105472 bytes

// Scratch (allocation-free: __device__ globals)
__device__ float g_h1[(size_t)N_NODES * D];
__device__ int   g_count[N_NODES];
__device__ int   g_off[N_NODES + 1];
__device__ int   g_cursor[N_NODES];
__device__ int   g_nbr[N_EDGES];
__device__ float g_inv[N_NODES];
__device__ int   g_blocksums[NBLK_SCAN];

// ---------------------------------------------------------------------------
// helpers
// ---------------------------------------------------------------------------
__device__ __forceinline__ void mma_bf16(float* d, const uint32_t* a,
                                         uint32_t b0, uint32_t b1) {
    asm volatile(
        "mma.sync.aligned.m16n8k16.row.col.f32.bf16.bf16.f32 "
        "{%0,%1,%2,%3}, {%4,%5,%6,%7}, {%8,%9}, {%0,%1,%2,%3};"
        : "+f"(d[0]), "+f"(d[1]), "+f"(d[2]), "+f"(d[3])
        : "r"(a[0]), "r"(a[1]), "r"(a[2]), "r"(a[3]), "r"(b0), "r"(b1));
}

__device__ __forceinline__ void bf_split(float v, unsigned short& h, unsigned short& l) {
    __nv_bfloat16 bh = __float2bfloat16(v);
    __nv_bfloat16 bl = __float2bfloat16(v - __bfloat162float(bh));
    h = __bfloat16_as_ushort(bh);
    l = __bfloat16_as_ushort(bl);
}
__device__ __forceinline__ uint32_t pack2(unsigned short a, unsigned short b) {
    return (uint32_t)a | ((uint32_t)b << 16);
}

// ---------------------------------------------------------------------------
// CSR construction (by destination)
// ---------------------------------------------------------------------------
__global__ void zero_count_kernel() {
    int i = blockIdx.x * blockDim.x + threadIdx.x;
    if (i < N_NODES) g_count[i] = 0;
}

__global__ void hist_kernel(const int* __restrict__ dst) {
    int e = blockIdx.x * blockDim.x + threadIdx.x;
    if (e < N_EDGES) atomicAdd(&g_count[dst[e]], 1);
}

__global__ void __launch_bounds__(1024) scan_block_kernel() {
    __shared__ int sh[1024];
    int gi = blockIdx.x * 1024 + threadIdx.x;
    int v = (gi < N_NODES) ? g_count[gi] : 0;
    sh[threadIdx.x] = v;
    __syncthreads();
#pragma unroll
    for (int off = 1; off < 1024; off <<= 1) {
        int t = (threadIdx.x >= off) ? sh[threadIdx.x - off] : 0;
        __syncthreads();
        sh[threadIdx.x] += t;
        __syncthreads();
    }
    int incl = sh[threadIdx.x];
    if (gi < N_NODES) g_off[gi] = incl - v;
    if (threadIdx.x == 1023) g_blocksums[blockIdx.x] = incl;
}

__global__ void __launch_bounds__(128) scan_top_kernel() {
    __shared__ int sh[128];
    int i = threadIdx.x;
    int v = (i < NBLK_SCAN) ? g_blocksums[i] : 0;
    sh[i] = v;
    __syncthreads();
#pragma unroll
    for (int off = 1; off < 128; off <<= 1) {
        int t = (i >= off) ? sh[i - off] : 0;
        __syncthreads();
        sh[i] += t;
        __syncthreads();
    }
    if (i < NBLK_SCAN) g_blocksums[i] = sh[i] - v;
}

__global__ void scan_finish_kernel() {
    int gi = blockIdx.x * blockDim.x + threadIdx.x;
    if (gi < N_NODES) {
        int o = g_off[gi] + g_blocksums[gi >> 10];
        g_off[gi] = o;
        g_cursor[gi] = o;
        int c = g_count[gi];
        g_inv[gi] = c > 0 ? 1.0f / (float)c : 0.f;
    }
    if (gi == 0) g_off[N_NODES] = N_EDGES;
}

__global__ void fill_kernel(const int* __restrict__ src,
                            const int* __restrict__ dst) {
    int e = blockIdx.x * blockDim.x + threadIdx.x;
    if (e < N_EDGES) {
        int p = atomicAdd(&g_cursor[dst[e]], 1);
        g_nbr[p] = src[e];
    }
}

// ---------------------------------------------------------------------------
// Fused tile kernel: gather -> bf16 hi/lo staging -> mma.sync GEMM -> epilogue
//   A = [mean_agg | feat]  (128 x 128), row-major, stride A_STRIDE halves
//   B = Wcat^T             (64 n-rows x 128 k), stride B_STRIDE halves
//   Y = relu(A @ B^T + bl)
// FINAL=false: Y -> g_h1 ;  FINAL=true: out = Y @ Wfc + bfc
// Block = 512 threads = 16 warps; warp w: m-band (w>>1)*16, n-half (w&1)*32.
// ---------------------------------------------------------------------------
template <bool FINAL>
__global__ void __launch_bounds__(512, 2) fused_tile_kernel(
    const float* __restrict__ xin,
    const float* __restrict__ Wl,
    const float* __restrict__ Wr,
    const float* __restrict__ bl,
    const float* __restrict__ Wfc,
    const float* __restrict__ bfc,
    float* __restrict__ outp) {
    extern __shared__ char smem[];
    float* sBias = (float*)(smem + SM_BIAS);
    float* sFc = (float*)(smem + SM_FC);
    float* sOut = (float*)(smem + SM_OUT);

    const int tid = threadIdx.x;
    const int wid = tid >> 5;
    const int lane = tid & 31;
    const int nbase = blockIdx.x * TILE_M;
    const float* feat = FINAL ? g_h1 : xin;

    if (tid < D) {
        sBias[tid] = bl[tid];
        if (FINAL) sFc[tid] = Wfc[tid];
    }
    if (FINAL && tid < TILE_M) sOut[tid] = 0.f;

    // ---- Stage weights (transposed, hi/lo): B[n][k] = Wcat[k][n] ----
#pragma unroll
    for (int it = 0; it < 8; it++) {
        int idx = tid + 512 * it;          // 4096 (n, k-pair) tasks
        int n = idx >> 6;
        int k0 = (idx & 63) * 2;
        float w0, w1;
        if (k0 < 64) { w0 = Wl[k0 * 64 + n];        w1 = Wl[(k0 + 1) * 64 + n]; }
        else         { w0 = Wr[(k0 - 64) * 64 + n]; w1 = Wr[(k0 - 63) * 64 + n]; }
        unsigned short h0, l0, h1, l1;
        bf_split(w0, h0, l0);
        bf_split(w1, h1, l1);
        *(uint32_t*)(smem + SM_BHI + ((size_t)n * B_STRIDE + k0) * 2) = pack2(h0, h1);
        *(uint32_t*)(smem + SM_BLO + ((size_t)n * B_STRIDE + k0) * 2) = pack2(l0, l1);
    }

    // ---- Stage X half (cols 64..127 of A) ----
#pragma unroll
    for (int r = 0; r < 8; r++) {
        int m = wid + 16 * r;
        int n = nbase + m;
        uint32_t ph = 0, pl = 0;
        if (n < N_NODES) {
            float2 v = ((const float2*)(feat + (size_t)n * D))[lane];
            unsigned short h0, l0, h1, l1;
            bf_split(v.x, h0, l0);
            bf_split(v.y, h1, l1);
            ph = pack2(h0, h1);
            pl = pack2(l0, l1);
        }
        size_t off = ((size_t)m * A_STRIDE + 64 + lane * 2) * 2;
        *(uint32_t*)(smem + SM_AHI + off) = ph;
        *(uint32_t*)(smem + SM_ALO + off) = pl;
    }

    // ---- Gather (cols 0..63 of A): mean over CSR neighbors ----
    {
        const int half = lane >> 4;
        const int c = lane & 15;
        const float4* feat4 = (const float4*)feat;
        for (int i = 0; i < 8; i++) {
            int m = wid + 16 * i;
            int n = nbase + m;
            float4 a0 = make_float4(0.f, 0.f, 0.f, 0.f);
            float4 a1 = make_float4(0.f, 0.f, 0.f, 0.f);
            if (n < N_NODES) {
                int jb = g_off[n], je = g_off[n + 1];
                int j = jb + half;
                for (; j + 2 < je; j += 4) {
                    int s0 = g_nbr[j];
                    int s1 = g_nbr[j + 2];
                    float4 v0 = feat4[(size_t)s0 * 16 + c];
                    float4 v1 = feat4[(size_t)s1 * 16 + c];
                    a0.x += v0.x; a0.y += v0.y; a0.z += v0.z; a0.w += v0.w;
                    a1.x += v1.x; a1.y += v1.y; a1.z += v1.z; a1.w += v1.w;
                }
                if (j < je) {
                    int s0 = g_nbr[j];
                    float4 v0 = feat4[(size_t)s0 * 16 + c];
                    a0.x += v0.x; a0.y += v0.y; a0.z += v0.z; a0.w += v0.w;
                }
            }
            a0.x += a1.x; a0.y += a1.y; a0.z += a1.z; a0.w += a1.w;
            a0.x += __shfl_down_sync(0xFFFFFFFFu, a0.x, 16);
            a0.y += __shfl_down_sync(0xFFFFFFFFu, a0.y, 16);
            a0.z += __shfl_down_sync(0xFFFFFFFFu, a0.z, 16);
            a0.w += __shfl_down_sync(0xFFFFFFFFu, a0.w, 16);
            if (half == 0) {
                float inv = (n < N_NODES) ? g_inv[n] : 0.f;
                a0.x *= inv; a0.y *= inv; a0.z *= inv; a0.w *= inv;
                unsigned short hx, lx, hy, ly, hz, lz, hw, lw;
                bf_split(a0.x, hx, lx);
                bf_split(a0.y, hy, ly);
                bf_split(a0.z, hz, lz);
                bf_split(a0.w, hw, lw);
                size_t off = ((size_t)m * A_STRIDE + 4 * c) * 2;
                *(uint2*)(smem + SM_AHI + off) = make_uint2(pack2(hx, hy), pack2(hz, hw));
                *(uint2*)(smem + SM_ALO + off) = make_uint2(pack2(lx, ly), pack2(lz, lw));
            }
        }
    }

    __syncthreads();

    // ---- Dense: Y = A @ B^T via mma.sync bf16, 3-pass hi/lo ----
    const int g = lane >> 2;
    const int t = lane & 3;
    const int mb = wid >> 1;      // m-band 0..7
    const int nh = wid & 1;       // n-half 0..1

    float acc[4][4];
#pragma unroll
    for (int s = 0; s < 4; s++)
#pragma unroll
        for (int q = 0; q < 4; q++) acc[s][q] = 0.f;

    const char* pAhi = smem + SM_AHI;
    const char* pAlo = smem + SM_ALO;
    const char* pBhi = smem + SM_BHI;
    const char* pBlo = smem + SM_BLO;
    const size_t rowA = (size_t)(mb * 16 + g) * A_STRIDE;
    const size_t rowA8 = rowA + (size_t)8 * A_STRIDE;

#pragma unroll
    for (int ks = 0; ks < 8; ks++) {
        const int k0 = ks * 16;
        uint32_t aHi[4], aLo[4];
        aHi[0] = *(const uint32_t*)(pAhi + (rowA + k0 + 2 * t) * 2);
        aHi[1] = *(const uint32_t*)(pAhi + (rowA8 + k0 + 2 * t) * 2);
        aHi[2] = *(const uint32_t*)(pAhi + (rowA + k0 + 8 + 2 * t) * 2);
        aHi[3] = *(const uint32_t*)(pAhi + (rowA8 + k0 + 8 + 2 * t) * 2);
        aLo[0] = *(const uint32_t*)(pAlo + (rowA + k0 + 2 * t) * 2);
        aLo[1] = *(const uint32_t*)(pAlo + (rowA8 + k0 + 2 * t) * 2);
        aLo[2] = *(const uint32_t*)(pAlo + (rowA + k0 + 8 + 2 * t) * 2);
        aLo[3] = *(const uint32_t*)(pAlo + (rowA8 + k0 + 8 + 2 * t) * 2);
#pragma unroll
        for (int sub = 0; sub < 4; sub++) {
            const int n = nh * 32 + sub * 8 + g;
            const size_t rowB = (size_t)n * B_STRIDE;
            uint32_t bh0 = *(const uint32_t*)(pBhi + (rowB + k0 + 2 * t) * 2);
            uint32_t bh1 = *(const uint32_t*)(pBhi + (rowB + k0 + 8 + 2 * t) * 2);
            uint32_t bl0 = *(const uint32_t*)(pBlo + (rowB + k0 + 2 * t) * 2);
            uint32_t bl1 = *(const uint32_t*)(pBlo + (rowB + k0 + 8 + 2 * t) * 2);
            mma_bf16(acc[sub], aHi, bh0, bh1);
            mma_bf16(acc[sub], aHi, bl0, bl1);
            mma_bf16(acc[sub], aLo, bh0, bh1);
        }
    }

    // ---- Epilogue ----
    const int m0 = mb * 16 + g;
    const int m1 = m0 + 8;
    if (!FINAL) {
#pragma unroll
        for (int sub = 0; sub < 4; sub++) {
            const int col = nh * 32 + sub * 8 + 2 * t;
            const float b0 = sBias[col];
            const float b1 = sBias[col + 1];
            const int n0 = nbase + m0;
            const int n1 = nbase + m1;
            if (n0 < N_NODES) {
                float2 v = make_float2(fmaxf(acc[sub][0] + b0, 0.f),
                                       fmaxf(acc[sub][1] + b1, 0.f));
                *(float2*)(g_h1 + (size_t)n0 * D + col) = v;
            }
            if (n1 < N_NODES) {
                float2 v = make_float2(fmaxf(acc[sub][2] + b0, 0.f),
                                       fmaxf(acc[sub][3] + b1, 0.f));
                *(float2*)(g_h1 + (size_t)n1 * D + col) = v;
            }
        }
    } else {
        float p0 = 0.f, p1 = 0.f;
#pragma unroll
        for (int sub = 0; sub < 4; sub++) {
            const int col = nh * 32 + sub * 8 + 2 * t;
            const float b0 = sBias[col];
            const float b1 = sBias[col + 1];
            const float f0 = sFc[col];
            const float f1 = sFc[col + 1];
            p0 += fmaxf(acc[sub][0] + b0, 0.f) * f0 + fmaxf(acc[sub][1] + b1, 0.f) * f1;
            p1 += fmaxf(acc[sub][2] + b0, 0.f) * f0 + fmaxf(acc[sub][3] + b1, 0.f) * f1;
        }
        // reduce over the 4 lanes of the quad (t = 0..3)
        p0 += __shfl_xor_sync(0xFFFFFFFFu, p0, 1);
        p0 += __shfl_xor_sync(0xFFFFFFFFu, p0, 2);
        p1 += __shfl_xor_sync(0xFFFFFFFFu, p1, 1);
        p1 += __shfl_xor_sync(0xFFFFFFFFu, p1, 2);
        if (t == 0) {
            atomicAdd(sOut + m0, p0);
            atomicAdd(sOut + m1, p1);
        }
        __syncthreads();
        if (tid < TILE_M) {
            int n = nbase + tid;
            if (n < N_NODES) outp[n] = sOut[tid] + bfc[0];
        }
    }
}

// ---------------------------------------------------------------------------
// Launch
// ---------------------------------------------------------------------------
extern "C" void kernel_launch(void* const* d_in, const int* in_sizes, int n_in,
                              void* d_out, int out_size) {
    const float* x = (const float*)d_in[0];
    const int* ei = (const int*)d_in[1];
    const float* Wl1 = (const float*)d_in[2];
    const float* bl1 = (const float*)d_in[3];
    const float* Wr1 = (const float*)d_in[4];
    const float* Wl2 = (const float*)d_in[5];
    const float* bl2 = (const float*)d_in[6];
    const float* Wr2 = (const float*)d_in[7];
    const float* Wfc = (const float*)d_in[8];
    const float* bfc = (const float*)d_in[9];
    float* out = (float*)d_out;

    const int* src = ei;
    const int* dst = ei + N_EDGES;

    const int nblk = (N_NODES + 255) / 256;
    const int eblk = (N_EDGES + 255) / 256;

    static int configured = 0;
    cudaFuncSetAttribute(fused_tile_kernel<false>,
                         cudaFuncAttributeMaxDynamicSharedMemorySize, SMEM_TOTAL);
    cudaFuncSetAttribute(fused_tile_kernel<true>,
                         cudaFuncAttributeMaxDynamicSharedMemorySize, SMEM_TOTAL);
    (void)configured;

    // CSR build (once per call; reused by both layers)
    zero_count_kernel<<<nblk, 256>>>();
    hist_kernel<<<eblk, 256>>>(dst);
    scan_block_kernel<<<NBLK_SCAN, 1024>>>();
    scan_top_kernel<<<1, 128>>>();
    scan_finish_kernel<<<nblk, 256>>>();
    fill_kernel<<<eblk, 256>>>(src, dst);

    // Layer 1 (fused gather + mma.sync dense)
    fused_tile_kernel<false><<<NODE_BLOCKS, 512, SMEM_TOTAL>>>(
        x, Wl1, Wr1, bl1, nullptr, nullptr, nullptr);

    // Layer 2 + head
    fused_tile_kernel<true><<<NODE_BLOCKS, 512, SMEM_TOTAL>>>(
        x, Wl2, Wr2, bl2, Wfc, bfc, out);
}